// round 9
// baseline (speedup 1.0000x reference)
#include <cuda_runtime.h>
#include <cstdint>

typedef unsigned long long ull;

#define PIDX(k,b) (((((k)>>1))<<6) + (((b))<<1) + ((k)&1))

// ---------------- device scratch ----------------
__device__ __align__(16) float g_xn [512*1024*32]; // xn packed  [t][d2][b][2]
__device__ __align__(16) float g_cx [512*1024*32]; // cfc_x packed
__device__ __align__(16) float g_co [512*1024*32]; // cfc_out packed
__device__ __align__(16) float g_pre[512*2048*32]; // L0 x-part preact [t][j][b]
__device__ __align__(16) float g_h  [1024*32];     // hidden packed
__device__ __align__(16) float g_b1 [2048*32];     // backbone L0 out packed
__device__ __align__(16) float g_b2 [2048*32];     // backbone L1 out packed
__device__ __align__(16) float g_winT [1024*1024]; // [j][k]
__device__ __align__(16) float g_w0T  [2048*2048];
__device__ __align__(16) float g_w1T  [2048*2048];
__device__ __align__(16) float g_whT  [4096*2048]; // interleaved heads rows
__device__ __align__(16) float g_woutT[1024*1024];
__device__ unsigned g_bar;

// ---------------- helpers ----------------
__device__ __forceinline__ ull f2fma(ull a, ull b, ull c) {
    ull d; asm("fma.rn.f32x2 %0,%1,%2,%3;" : "=l"(d) : "l"(a), "l"(b), "l"(c));
    return d;
}
__device__ __forceinline__ float2 u2f(ull v) {
    float2 f; asm("mov.b64 {%0,%1},%2;" : "=f"(f.x), "=f"(f.y) : "l"(v));
    return f;
}
__device__ __forceinline__ void cpa16(uint32_t s, const float* g) {
    asm volatile("cp.async.cg.shared.global [%0],[%1],16;" :: "r"(s), "l"(g));
}
__device__ __forceinline__ void cp_commit() { asm volatile("cp.async.commit_group;"); }

__device__ __forceinline__ void bar_arrive(unsigned& gen) {
    __syncthreads();
    gen++;
    if (threadIdx.x == 0) {
        __threadfence();
        atomicAdd(&g_bar, 1u);
    }
}
__device__ __forceinline__ void bar_wait(unsigned gen) {
    if (threadIdx.x == 0) {
        unsigned tgt = gen * gridDim.x;
        unsigned v;
        do {
            asm volatile("ld.acquire.gpu.u32 %0,[%1];" : "=r"(v) : "l"(&g_bar) : "memory");
        } while (v < tgt);
    }
    __syncthreads();
}

// ---------------- fused transposes (+ g_bar reset) ----------------
__global__ __launch_bounds__(256) void k_tr(const float* __restrict__ bbw,
                                            const float* __restrict__ win,
                                            const float* __restrict__ wout,
                                            const float* __restrict__ wf1,
                                            const float* __restrict__ wf2,
                                            const float* __restrict__ wta,
                                            const float* __restrict__ wtb) {
    __shared__ float tile[32][33];
    int z = blockIdx.z;
    int c0 = blockIdx.x * 32, r0 = blockIdx.y * 32;
    int x = threadIdx.x, y = threadIdx.y;
    if (z == 0 && blockIdx.x == 0 && blockIdx.y == 0 && threadIdx.x == 0 && threadIdx.y == 0)
        g_bar = 0u;
    if (z < 2) {
        const float* src = bbw + (size_t)z * 4194304;
        float* dst = z ? g_w1T : g_w0T;
#pragma unroll
        for (int i = 0; i < 32; i += 8)
            tile[y + i][x] = src[(size_t)(r0 + y + i) * 2048 + c0 + x];
        __syncthreads();
#pragma unroll
        for (int i = 0; i < 32; i += 8)
            dst[(size_t)(c0 + y + i) * 2048 + r0 + x] = tile[x][y + i];
    } else if (z < 4) {
        if (blockIdx.x >= 32 || blockIdx.y >= 32) return;
        const float* src = (z == 3) ? wout : win;
        float* dst = (z == 3) ? g_woutT : g_winT;
#pragma unroll
        for (int i = 0; i < 32; i += 8)
            tile[y + i][x] = src[(size_t)(r0 + y + i) * 1024 + c0 + x];
        __syncthreads();
#pragma unroll
        for (int i = 0; i < 32; i += 8)
            dst[(size_t)(c0 + y + i) * 1024 + r0 + x] = tile[x][y + i];
    } else {
        if (blockIdx.x >= 32) return;
        int h = z - 4;
        const float* src = h == 0 ? wf1 : h == 1 ? wf2 : h == 2 ? wta : wtb;
#pragma unroll
        for (int i = 0; i < 32; i += 8)
            tile[y + i][x] = src[(size_t)(r0 + y + i) * 1024 + c0 + x];
        __syncthreads();
#pragma unroll
        for (int i = 0; i < 32; i += 8) {
            int j = c0 + y + i;
            int f = ((j >> 3) << 5) + h * 8 + (j & 7);
            g_whT[(size_t)f * 2048 + r0 + x] = tile[x][y + i];
        }
    }
}

// ---------------- layernorm -> packed xn ----------------
__global__ __launch_bounds__(256) void k_ln(const float* __restrict__ x,
                                            const float* __restrict__ nw,
                                            const float* __restrict__ nb) {
    const int t = blockIdx.x;
    __shared__ float smu[32], srs[32];
    int warp = threadIdx.x >> 5, lane = threadIdx.x & 31;
    for (int b = warp; b < 32; b += 8) {
        const float* row = x + (size_t)b * 524288 + (size_t)t * 1024;
        float s = 0.f, s2 = 0.f;
        for (int d = lane; d < 1024; d += 32) { float v = row[d]; s += v; s2 += v * v; }
#pragma unroll
        for (int o = 16; o; o >>= 1) {
            s  += __shfl_xor_sync(0xffffffffu, s, o);
            s2 += __shfl_xor_sync(0xffffffffu, s2, o);
        }
        if (lane == 0) {
            float mu = s * (1.f / 1024.f);
            float var = s2 * (1.f / 1024.f) - mu * mu;
            smu[b] = mu; srs[b] = rsqrtf(var + 1e-5f);
        }
    }
    __syncthreads();
    float* dst = g_xn + (size_t)t * 32768;
    for (int b = warp; b < 32; b += 8) {
        const float* row = x + (size_t)b * 524288 + (size_t)t * 1024;
        float mu = smu[b], rs = srs[b];
        for (int d = lane; d < 1024; d += 32)
            dst[PIDX(d, b)] = (row[d] - mu) * rs * nw[d] + nb[d];
    }
}

// ---------------- input projection: cfc_x = xn @ w_inT + b_in ----------------
__global__ __launch_bounds__(256) void k_gin(const float* __restrict__ bias) {
    const int tid = threadIdx.x, warp = tid >> 5, lane = tid & 31;
    const int j0 = blockIdx.x * 64 + warp * 8;
    const int t0 = blockIdx.y * 4;
    ull acc[4][8];
#pragma unroll
    for (int tt = 0; tt < 4; tt++)
#pragma unroll
        for (int j = 0; j < 8; j++) acc[tt][j] = 0ull;
    const ull* xp = (const ull*)g_xn;
#pragma unroll 1
    for (int k4 = 0; k4 < 256; k4++) {
        ull a0[4], a1[4];
#pragma unroll
        for (int tt = 0; tt < 4; tt++) {
            const ull* ap = xp + (size_t)(t0 + tt) * 16384 + (size_t)(2 * k4) * 32;
            a0[tt] = ap[lane]; a1[tt] = ap[lane + 32];
        }
#pragma unroll
        for (int j = 0; j < 8; j++) {
            ulonglong2 wv = *(const ulonglong2*)(g_winT + (size_t)(j0 + j) * 1024 + 4 * k4);
#pragma unroll
            for (int tt = 0; tt < 4; tt++) {
                acc[tt][j] = f2fma(a0[tt], wv.x, acc[tt][j]);
                acc[tt][j] = f2fma(a1[tt], wv.y, acc[tt][j]);
            }
        }
    }
#pragma unroll
    for (int tt = 0; tt < 4; tt++)
#pragma unroll
        for (int j = 0; j < 8; j++) {
            float2 s = u2f(acc[tt][j]);
            g_cx[(size_t)(t0 + tt) * 32768 + PIDX(j0 + j, lane)] = s.x + s.y + bias[j0 + j];
        }
}

// ---------------- L0 x-part pre-activation: pre = cfc_x @ W0x + b0 ----------
__global__ __launch_bounds__(256) void k_pre(const float* __restrict__ bbb) {
    const int tid = threadIdx.x, warp = tid >> 5, lane = tid & 31;
    const int j0 = blockIdx.x * 64 + warp * 8;
    const int t0 = blockIdx.y * 4;
    ull acc[4][8];
#pragma unroll
    for (int tt = 0; tt < 4; tt++)
#pragma unroll
        for (int j = 0; j < 8; j++) acc[tt][j] = 0ull;
    const ull* cxp = (const ull*)g_cx;
#pragma unroll 1
    for (int k4 = 0; k4 < 256; k4++) {
        ull a0[4], a1[4];
#pragma unroll
        for (int tt = 0; tt < 4; tt++) {
            const ull* ap = cxp + (size_t)(t0 + tt) * 16384 + (size_t)(2 * k4) * 32;
            a0[tt] = ap[lane]; a1[tt] = ap[lane + 32];
        }
#pragma unroll
        for (int j = 0; j < 8; j++) {
            ulonglong2 wv = *(const ulonglong2*)(g_w0T + (size_t)(j0 + j) * 2048 + 4 * k4);
#pragma unroll
            for (int tt = 0; tt < 4; tt++) {
                acc[tt][j] = f2fma(a0[tt], wv.x, acc[tt][j]);
                acc[tt][j] = f2fma(a1[tt], wv.y, acc[tt][j]);
            }
        }
    }
#pragma unroll
    for (int tt = 0; tt < 4; tt++)
#pragma unroll
        for (int j = 0; j < 8; j++) {
            float2 s = u2f(acc[tt][j]);
            g_pre[(size_t)(t0 + tt) * 65536 + (size_t)(j0 + j) * 32 + lane] =
                s.x + s.y + bbb[j0 + j];
        }
}

// ---------------- output projection + residual ----------------
__global__ __launch_bounds__(256) void k_gout(const float* __restrict__ bias,
                                              const float* __restrict__ x,
                                              float* __restrict__ y) {
    const int tid = threadIdx.x, warp = tid >> 5, lane = tid & 31;
    const int j0 = blockIdx.x * 64 + warp * 8;
    const int t0 = blockIdx.y * 4;
    ull acc[4][8];
#pragma unroll
    for (int tt = 0; tt < 4; tt++)
#pragma unroll
        for (int j = 0; j < 8; j++) acc[tt][j] = 0ull;
    const ull* cp = (const ull*)g_co;
#pragma unroll 1
    for (int k4 = 0; k4 < 256; k4++) {
        ull a0[4], a1[4];
#pragma unroll
        for (int tt = 0; tt < 4; tt++) {
            const ull* ap = cp + (size_t)(t0 + tt) * 16384 + (size_t)(2 * k4) * 32;
            a0[tt] = ap[lane]; a1[tt] = ap[lane + 32];
        }
#pragma unroll
        for (int j = 0; j < 8; j++) {
            ulonglong2 wv = *(const ulonglong2*)(g_woutT + (size_t)(j0 + j) * 1024 + 4 * k4);
#pragma unroll
            for (int tt = 0; tt < 4; tt++) {
                acc[tt][j] = f2fma(a0[tt], wv.x, acc[tt][j]);
                acc[tt][j] = f2fma(a1[tt], wv.y, acc[tt][j]);
            }
        }
    }
#pragma unroll
    for (int tt = 0; tt < 4; tt++)
#pragma unroll
        for (int j = 0; j < 8; j++) {
            int d = j0 + j;
            size_t oi = (size_t)lane * 524288 + (size_t)(t0 + tt) * 1024 + d;
            float2 s = u2f(acc[tt][j]);
            y[oi] = s.x + s.y + bias[d] + x[oi];
        }
}

// ---------------- scan smem layout (floats), 512 threads ----------------
//  wb   : 3 x 4096  (weight tiles, 16 rows x 256 k)
//  ab   : 3 x 8192  (act tiles, 256 k x 32 b)
//  sred : 8192      (8 slots x 16 rows x 32 + sHa/sHb at +4096/+4608)
#define SM_WB 0
#define SM_AB 12288
#define SM_SR 36864
#define SCAN_SMEM 180224

__device__ __forceinline__ void pfW(float* smem, int buf, const float* Wt, int tid) {
    uint32_t sw = (uint32_t)__cvta_generic_to_shared(smem + SM_WB + buf * 4096);
#pragma unroll
    for (int r = 0; r < 2; r++) {
        int o = r * 512 + tid;            // 0..1023
        int row = o >> 6, c = (o & 63) << 2;
        cpa16(sw + (uint32_t)(row * 256 + c) * 4u, Wt + (size_t)row * 2048 + c);
    }
}
__device__ __forceinline__ void pfA(float* smem, int buf, const float* At, int tid) {
    uint32_t sa = (uint32_t)__cvta_generic_to_shared(smem + SM_AB + buf * 8192);
#pragma unroll
    for (int r = 0; r < 4; r++) {
        int o = r * 512 + tid;            // 0..2047
        cpa16(sa + (uint32_t)o * 16u, At + o * 4);
    }
}

// caller must have already committed W tiles 0 (buf0) and 1 (buf1).
// leaves 8 partial slots in sred ([slot][16 rows][32 lanes]).
template<int NT>
__device__ __forceinline__ void gemm_phase(
    float* smem, const float* Wbase, const float* act,
    int warp, int lane, int tid)
{
    pfA(smem, 0, act, tid);        cp_commit();
    pfA(smem, 1, act + 8192, tid); cp_commit();
    ull acc[16];
#pragma unroll
    for (int j = 0; j < 16; j++) acc[j] = 0ull;
#pragma unroll 1
    for (int kt = 0; kt < NT; kt++) {
        if (kt < NT - 1) asm volatile("cp.async.wait_group 1;");
        else             asm volatile("cp.async.wait_group 0;");
        __syncthreads();
        if (kt < NT - 2) {
            int n = kt + 2;
            pfW(smem, n % 3, Wbase + n * 256, tid);
            pfA(smem, n % 3, act + n * 8192, tid);
            cp_commit();
        }
        const float* w = smem + SM_WB + (kt % 3) * 4096;
        const ull* au = (const ull*)(smem + SM_AB + (kt % 3) * 8192);
        const int k2lo = warp * 8;
#pragma unroll
        for (int k2 = 0; k2 < 8; k2 += 2) {
            ull a0 = au[(k2lo + k2) * 32 + lane];
            ull a1 = au[(k2lo + k2 + 1) * 32 + lane];
#pragma unroll
            for (int j = 0; j < 16; j++) {
                ulonglong2 wv = *(const ulonglong2*)(w + j * 256 + (k2lo + k2) * 2);
                acc[j] = f2fma(a0, wv.x, acc[j]);
                acc[j] = f2fma(a1, wv.y, acc[j]);
            }
        }
    }
    float v[16];
#pragma unroll
    for (int j = 0; j < 16; j++) {
        float2 p = u2f(acc[j]);
        v[j] = p.x + p.y;
    }
    float* sred = smem + SM_SR;
    __syncthreads();
    if (warp >= 8) {
#pragma unroll
        for (int j = 0; j < 16; j++)
            sred[((warp - 8) * 16 + j) * 32 + lane] = v[j];
    }
    __syncthreads();
    if (warp < 8) {
#pragma unroll
        for (int j = 0; j < 16; j++)
            sred[(warp * 16 + j) * 32 + lane] += v[j];
    }
    __syncthreads();
}

// ---------------- persistent CfC scan (512 threads) ----------------
extern __shared__ float s_dyn[];

__global__ __launch_bounds__(512, 1) void k_scan(const float* __restrict__ tsp,
                                                 const float* __restrict__ hid,
                                                 const float* __restrict__ bbb,
                                                 const float* __restrict__ bf1,
                                                 const float* __restrict__ bf2,
                                                 const float* __restrict__ bta,
                                                 const float* __restrict__ btb) {
    float* smem = s_dyn;
    float* sred = smem + SM_SR;
    float* sHa  = sred + 4096;
    float* sHb  = sred + 4608;
    const int tid = threadIdx.x, warp = tid >> 5, lane = tid & 31, bid = blockIdx.x;
    unsigned gen = 0;
    const int j0 = bid * 16;
    const int u0 = bid * 8;
    const float* W0h = g_w0T + (size_t)j0 * 2048 + 1024;    // h-part rows, stride 2048
    const float* W1  = g_w1T + (size_t)j0 * 2048;
    const float* WhA = g_whT + (size_t)bid * 32 * 2048;
    const float* WhB = WhA + 16 * 2048;
    {   // init hidden
        int i = bid * 512 + tid;
        if (i < 32768) {
            int u = i >> 5, b = i & 31;
            g_h[PIDX(u, b)] = hid[b * 1024 + u];
        }
    }
    bar_arrive(gen);
    pfW(smem, 0, W0h, tid);       cp_commit();
    pfW(smem, 1, W0h + 256, tid); cp_commit();
    bar_wait(gen);

    for (int t = 0; t < 512; t++) {
        // ---- backbone layer 0, h-part only (K=1024) ----
        gemm_phase<4>(smem, W0h, g_h, warp, lane, tid);
        {
            int jj = warp;
            float s = g_pre[(size_t)t * 65536 + (size_t)(j0 + jj) * 32 + lane];
#pragma unroll
            for (int w8 = 0; w8 < 8; w8++) s += sred[(w8 * 16 + jj) * 32 + lane];
            g_b1[PIDX(j0 + jj, lane)] = 1.7159f * tanhf(0.666f * s);
        }
        bar_arrive(gen);
        pfW(smem, 0, W1, tid);       cp_commit();
        pfW(smem, 1, W1 + 256, tid); cp_commit();
        bar_wait(gen);
        // ---- backbone layer 1 (K=2048) ----
        gemm_phase<8>(smem, W1, g_b1, warp, lane, tid);
        {
            int jj = warp;
            float s = bbb[2048 + j0 + jj];
#pragma unroll
            for (int w8 = 0; w8 < 8; w8++) s += sred[(w8 * 16 + jj) * 32 + lane];
            g_b2[PIDX(j0 + jj, lane)] = 1.7159f * tanhf(0.666f * s);
        }
        bar_arrive(gen);
        pfW(smem, 0, WhA, tid);       cp_commit();
        pfW(smem, 1, WhA + 256, tid); cp_commit();
        bar_wait(gen);
        // ---- heads pass A: ff1|ff2 rows (block-local) ----
        gemm_phase<8>(smem, WhA, g_b2, warp, lane, tid);
        pfW(smem, 0, WhB, tid);       cp_commit();
        pfW(smem, 1, WhB + 256, tid); cp_commit();
        {
            int jj = warp;
            int u = u0 + (jj & 7);
            float s = (jj < 8) ? bf1[u] : bf2[u];
#pragma unroll
            for (int w8 = 0; w8 < 8; w8++) s += sred[(w8 * 16 + jj) * 32 + lane];
            sHa[jj * 32 + lane] = s;
        }
        // ---- heads pass B: ta|tb rows (block-local) ----
        gemm_phase<8>(smem, WhB, g_b2, warp, lane, tid);
        {
            int jj = warp;
            int u = u0 + (jj & 7);
            float s = (jj < 8) ? bta[u] : btb[u];
#pragma unroll
            for (int w8 = 0; w8 < 8; w8++) s += sred[(w8 * 16 + jj) * 32 + lane];
            sHb[jj * 32 + lane] = s;
        }
        __syncthreads();
        if (warp < 8) {   // fused CfC gate: this block's 8 u-units x 32 batches
            float v1 = tanhf(sHa[warp * 32 + lane]);
            float v2 = tanhf(sHa[(8 + warp) * 32 + lane]);
            float ta = sHb[warp * 32 + lane];
            float tb = sHb[(8 + warp) * 32 + lane];
            float ts = tsp[lane * 512 + t];
            float ti = 1.f / (1.f + expf(-(ta * ts + tb)));
            float hn = v1 + ti * (v2 - v1);
            int p = PIDX(u0 + warp, lane);
            g_h[p] = hn;
            g_co[(size_t)t * 32768 + p] = hn;
        }
        bar_arrive(gen);
        if (t != 511) {
            pfW(smem, 0, W0h, tid);       cp_commit();
            pfW(smem, 1, W0h + 256, tid); cp_commit();
        }
        bar_wait(gen);
    }
}

// ---------------- h_final writeback ----------------
__global__ void k_hf(float* __restrict__ out) {
    int i = blockIdx.x * 256 + threadIdx.x;
    int u = i & 1023, b = i >> 10;
    out[i] = g_h[PIDX(u, b)];
}

// ---------------- host ----------------
extern "C" void kernel_launch(void* const* d_in, const int* in_sizes, int n_in,
                              void* d_out, int out_size) {
    const float* x    = (const float*)d_in[0];
    const float* tsp  = (const float*)d_in[1];
    const float* hid  = (const float*)d_in[2];
    const float* nw   = (const float*)d_in[3];
    const float* nb   = (const float*)d_in[4];
    const float* w_in = (const float*)d_in[5];
    const float* b_in = (const float*)d_in[6];
    const float* bbw  = (const float*)d_in[7];
    const float* bbb  = (const float*)d_in[8];
    const float* wf1  = (const float*)d_in[9];
    const float* bf1  = (const float*)d_in[10];
    const float* wf2  = (const float*)d_in[11];
    const float* bf2  = (const float*)d_in[12];
    const float* wta  = (const float*)d_in[13];
    const float* bta  = (const float*)d_in[14];
    const float* wtb  = (const float*)d_in[15];
    const float* btb  = (const float*)d_in[16];
    const float* w_out= (const float*)d_in[17];
    const float* b_out= (const float*)d_in[18];
    float* y  = (float*)d_out;
    float* hf = y + 16777216;

    static int s_attr_set = 0;
    if (!s_attr_set) {
        cudaFuncSetAttribute(k_scan, cudaFuncAttributeMaxDynamicSharedMemorySize, SCAN_SMEM);
        s_attr_set = 1;
    }

    dim3 tb(32, 8);
    k_tr<<<dim3(64, 64, 8), tb>>>(bbw, w_in, w_out, wf1, wf2, wta, wtb);
    k_ln<<<512, 256>>>(x, nw, nb);
    k_gin<<<dim3(16, 128), 256>>>(b_in);
    k_pre<<<dim3(32, 128), 256>>>(bbb);
    k_scan<<<128, 512, SCAN_SMEM>>>(tsp, hid, bbb, bf1, bf2, bta, btb);
    k_gout<<<dim3(16, 128), 256>>>(b_out, x, y);
    k_hf<<<128, 256>>>(hf);
}

// round 10
// speedup vs baseline: 1.0448x; 1.0448x over previous
#include <cuda_runtime.h>
#include <cstdint>

typedef unsigned long long ull;

#define PIDX(k,b) (((((k)>>1))<<6) + (((b))<<1) + ((k)&1))

// ---------------- device scratch ----------------
__device__ __align__(16) float g_xn [512*1024*32]; // xn packed  [t][d2][b][2]
__device__ __align__(16) float g_cx [512*1024*32]; // cfc_x packed
__device__ __align__(16) float g_co [512*1024*32]; // cfc_out packed
__device__ __align__(16) float g_pre[512*2048*32]; // L0 x-part preact [t][j][b]
__device__ __align__(16) float g_h  [1024*32];     // hidden packed
__device__ __align__(16) float g_b1 [2048*32];     // backbone L0 out packed
__device__ __align__(16) float g_b2 [2048*32];     // backbone L1 out packed
__device__ __align__(16) float g_winT [1024*1024]; // [j][k]
__device__ __align__(16) float g_w0T  [2048*2048];
__device__ __align__(16) float g_w1T  [2048*2048];
__device__ __align__(16) float g_whT  [4096*2048]; // interleaved heads rows
__device__ __align__(16) float g_woutT[1024*1024];
__device__ unsigned g_bar;

// ---------------- helpers ----------------
__device__ __forceinline__ ull f2fma(ull a, ull b, ull c) {
    ull d; asm("fma.rn.f32x2 %0,%1,%2,%3;" : "=l"(d) : "l"(a), "l"(b), "l"(c));
    return d;
}
__device__ __forceinline__ float2 u2f(ull v) {
    float2 f; asm("mov.b64 {%0,%1},%2;" : "=f"(f.x), "=f"(f.y) : "l"(v));
    return f;
}
__device__ __forceinline__ void cpa16(uint32_t s, const float* g) {
    asm volatile("cp.async.cg.shared.global [%0],[%1],16;" :: "r"(s), "l"(g));
}
__device__ __forceinline__ void cp_commit() { asm volatile("cp.async.commit_group;"); }

__device__ __forceinline__ void bar_arrive(unsigned& gen) {
    __syncthreads();
    gen++;
    if (threadIdx.x == 0) {
        __threadfence();
        atomicAdd(&g_bar, 1u);
    }
}
__device__ __forceinline__ void bar_wait(unsigned gen) {
    if (threadIdx.x == 0) {
        unsigned tgt = gen * gridDim.x;
        unsigned v;
        do {
            asm volatile("ld.acquire.gpu.u32 %0,[%1];" : "=r"(v) : "l"(&g_bar) : "memory");
        } while (v < tgt);
    }
    __syncthreads();
}

// ---------------- fused transposes (+ g_bar reset) ----------------
__global__ __launch_bounds__(256) void k_tr(const float* __restrict__ bbw,
                                            const float* __restrict__ win,
                                            const float* __restrict__ wout,
                                            const float* __restrict__ wf1,
                                            const float* __restrict__ wf2,
                                            const float* __restrict__ wta,
                                            const float* __restrict__ wtb) {
    __shared__ float tile[32][33];
    int z = blockIdx.z;
    int c0 = blockIdx.x * 32, r0 = blockIdx.y * 32;
    int x = threadIdx.x, y = threadIdx.y;
    if (z == 0 && blockIdx.x == 0 && blockIdx.y == 0 && threadIdx.x == 0 && threadIdx.y == 0)
        g_bar = 0u;
    if (z < 2) {
        const float* src = bbw + (size_t)z * 4194304;
        float* dst = z ? g_w1T : g_w0T;
#pragma unroll
        for (int i = 0; i < 32; i += 8)
            tile[y + i][x] = src[(size_t)(r0 + y + i) * 2048 + c0 + x];
        __syncthreads();
#pragma unroll
        for (int i = 0; i < 32; i += 8)
            dst[(size_t)(c0 + y + i) * 2048 + r0 + x] = tile[x][y + i];
    } else if (z < 4) {
        if (blockIdx.x >= 32 || blockIdx.y >= 32) return;
        const float* src = (z == 3) ? wout : win;
        float* dst = (z == 3) ? g_woutT : g_winT;
#pragma unroll
        for (int i = 0; i < 32; i += 8)
            tile[y + i][x] = src[(size_t)(r0 + y + i) * 1024 + c0 + x];
        __syncthreads();
#pragma unroll
        for (int i = 0; i < 32; i += 8)
            dst[(size_t)(c0 + y + i) * 1024 + r0 + x] = tile[x][y + i];
    } else {
        if (blockIdx.x >= 32) return;
        int h = z - 4;
        const float* src = h == 0 ? wf1 : h == 1 ? wf2 : h == 2 ? wta : wtb;
#pragma unroll
        for (int i = 0; i < 32; i += 8)
            tile[y + i][x] = src[(size_t)(r0 + y + i) * 1024 + c0 + x];
        __syncthreads();
#pragma unroll
        for (int i = 0; i < 32; i += 8) {
            int j = c0 + y + i;
            int f = ((j >> 3) << 5) + h * 8 + (j & 7);
            g_whT[(size_t)f * 2048 + r0 + x] = tile[x][y + i];
        }
    }
}

// ---------------- layernorm -> packed xn ----------------
__global__ __launch_bounds__(256) void k_ln(const float* __restrict__ x,
                                            const float* __restrict__ nw,
                                            const float* __restrict__ nb) {
    const int t = blockIdx.x;
    __shared__ float smu[32], srs[32];
    int warp = threadIdx.x >> 5, lane = threadIdx.x & 31;
    for (int b = warp; b < 32; b += 8) {
        const float* row = x + (size_t)b * 524288 + (size_t)t * 1024;
        float s = 0.f, s2 = 0.f;
        for (int d = lane; d < 1024; d += 32) { float v = row[d]; s += v; s2 += v * v; }
#pragma unroll
        for (int o = 16; o; o >>= 1) {
            s  += __shfl_xor_sync(0xffffffffu, s, o);
            s2 += __shfl_xor_sync(0xffffffffu, s2, o);
        }
        if (lane == 0) {
            float mu = s * (1.f / 1024.f);
            float var = s2 * (1.f / 1024.f) - mu * mu;
            smu[b] = mu; srs[b] = rsqrtf(var + 1e-5f);
        }
    }
    __syncthreads();
    float* dst = g_xn + (size_t)t * 32768;
    for (int b = warp; b < 32; b += 8) {
        const float* row = x + (size_t)b * 524288 + (size_t)t * 1024;
        float mu = smu[b], rs = srs[b];
        for (int d = lane; d < 1024; d += 32)
            dst[PIDX(d, b)] = (row[d] - mu) * rs * nw[d] + nb[d];
    }
}

// ---------------- input projection: cfc_x = xn @ w_inT + b_in ----------------
__global__ __launch_bounds__(256) void k_gin(const float* __restrict__ bias) {
    const int tid = threadIdx.x, warp = tid >> 5, lane = tid & 31;
    const int j0 = blockIdx.x * 64 + warp * 8;
    const int t0 = blockIdx.y * 4;
    ull acc[4][8];
#pragma unroll
    for (int tt = 0; tt < 4; tt++)
#pragma unroll
        for (int j = 0; j < 8; j++) acc[tt][j] = 0ull;
    const ull* xp = (const ull*)g_xn;
#pragma unroll 1
    for (int k4 = 0; k4 < 256; k4++) {
        ull a0[4], a1[4];
#pragma unroll
        for (int tt = 0; tt < 4; tt++) {
            const ull* ap = xp + (size_t)(t0 + tt) * 16384 + (size_t)(2 * k4) * 32;
            a0[tt] = ap[lane]; a1[tt] = ap[lane + 32];
        }
#pragma unroll
        for (int j = 0; j < 8; j++) {
            ulonglong2 wv = *(const ulonglong2*)(g_winT + (size_t)(j0 + j) * 1024 + 4 * k4);
#pragma unroll
            for (int tt = 0; tt < 4; tt++) {
                acc[tt][j] = f2fma(a0[tt], wv.x, acc[tt][j]);
                acc[tt][j] = f2fma(a1[tt], wv.y, acc[tt][j]);
            }
        }
    }
#pragma unroll
    for (int tt = 0; tt < 4; tt++)
#pragma unroll
        for (int j = 0; j < 8; j++) {
            float2 s = u2f(acc[tt][j]);
            g_cx[(size_t)(t0 + tt) * 32768 + PIDX(j0 + j, lane)] = s.x + s.y + bias[j0 + j];
        }
}

// ---------------- L0 x-part pre-activation: pre = cfc_x @ W0x + b0 ----------
__global__ __launch_bounds__(256) void k_pre(const float* __restrict__ bbb) {
    const int tid = threadIdx.x, warp = tid >> 5, lane = tid & 31;
    const int j0 = blockIdx.x * 64 + warp * 8;
    const int t0 = blockIdx.y * 4;
    ull acc[4][8];
#pragma unroll
    for (int tt = 0; tt < 4; tt++)
#pragma unroll
        for (int j = 0; j < 8; j++) acc[tt][j] = 0ull;
    const ull* cxp = (const ull*)g_cx;
#pragma unroll 1
    for (int k4 = 0; k4 < 256; k4++) {
        ull a0[4], a1[4];
#pragma unroll
        for (int tt = 0; tt < 4; tt++) {
            const ull* ap = cxp + (size_t)(t0 + tt) * 16384 + (size_t)(2 * k4) * 32;
            a0[tt] = ap[lane]; a1[tt] = ap[lane + 32];
        }
#pragma unroll
        for (int j = 0; j < 8; j++) {
            ulonglong2 wv = *(const ulonglong2*)(g_w0T + (size_t)(j0 + j) * 2048 + 4 * k4);
#pragma unroll
            for (int tt = 0; tt < 4; tt++) {
                acc[tt][j] = f2fma(a0[tt], wv.x, acc[tt][j]);
                acc[tt][j] = f2fma(a1[tt], wv.y, acc[tt][j]);
            }
        }
    }
#pragma unroll
    for (int tt = 0; tt < 4; tt++)
#pragma unroll
        for (int j = 0; j < 8; j++) {
            float2 s = u2f(acc[tt][j]);
            g_pre[(size_t)(t0 + tt) * 65536 + (size_t)(j0 + j) * 32 + lane] =
                s.x + s.y + bbb[j0 + j];
        }
}

// ---------------- output projection + residual ----------------
__global__ __launch_bounds__(256) void k_gout(const float* __restrict__ bias,
                                              const float* __restrict__ x,
                                              float* __restrict__ y) {
    const int tid = threadIdx.x, warp = tid >> 5, lane = tid & 31;
    const int j0 = blockIdx.x * 64 + warp * 8;
    const int t0 = blockIdx.y * 4;
    ull acc[4][8];
#pragma unroll
    for (int tt = 0; tt < 4; tt++)
#pragma unroll
        for (int j = 0; j < 8; j++) acc[tt][j] = 0ull;
    const ull* cp = (const ull*)g_co;
#pragma unroll 1
    for (int k4 = 0; k4 < 256; k4++) {
        ull a0[4], a1[4];
#pragma unroll
        for (int tt = 0; tt < 4; tt++) {
            const ull* ap = cp + (size_t)(t0 + tt) * 16384 + (size_t)(2 * k4) * 32;
            a0[tt] = ap[lane]; a1[tt] = ap[lane + 32];
        }
#pragma unroll
        for (int j = 0; j < 8; j++) {
            ulonglong2 wv = *(const ulonglong2*)(g_woutT + (size_t)(j0 + j) * 1024 + 4 * k4);
#pragma unroll
            for (int tt = 0; tt < 4; tt++) {
                acc[tt][j] = f2fma(a0[tt], wv.x, acc[tt][j]);
                acc[tt][j] = f2fma(a1[tt], wv.y, acc[tt][j]);
            }
        }
    }
#pragma unroll
    for (int tt = 0; tt < 4; tt++)
#pragma unroll
        for (int j = 0; j < 8; j++) {
            int d = j0 + j;
            size_t oi = (size_t)lane * 524288 + (size_t)(t0 + tt) * 1024 + d;
            float2 s = u2f(acc[tt][j]);
            y[oi] = s.x + s.y + bias[d] + x[oi];
        }
}

// ---------------- scan smem layout (floats), 512 threads ----------------
//  wb   : 3 x 4096  (weight tiles, 16 rows x 256 k)
//  ab   : 3 x 8192  (act tiles, 256 k x 32 b)
//  sred : 8192      (8 slots x 16 rows x 32 + sHa/sHb at +4096/+4608)
#define SM_WB 0
#define SM_AB 12288
#define SM_SR 36864
#define SCAN_SMEM 180224

__device__ __forceinline__ void pfW(float* smem, int buf, const float* Wt, int tid) {
    uint32_t sw = (uint32_t)__cvta_generic_to_shared(smem + SM_WB + buf * 4096);
#pragma unroll
    for (int r = 0; r < 2; r++) {
        int o = r * 512 + tid;            // 0..1023
        int row = o >> 6, c = (o & 63) << 2;
        cpa16(sw + (uint32_t)(row * 256 + c) * 4u, Wt + (size_t)row * 2048 + c);
    }
}
__device__ __forceinline__ void pfA(float* smem, int buf, const float* At, int tid) {
    uint32_t sa = (uint32_t)__cvta_generic_to_shared(smem + SM_AB + buf * 8192);
#pragma unroll
    for (int r = 0; r < 4; r++) {
        int o = r * 512 + tid;            // 0..2047
        cpa16(sa + (uint32_t)o * 16u, At + o * 4);
    }
}

// caller must have already committed W tiles 0 (buf0) and 1 (buf1).
// leaves 8 partial slots in sred ([slot][16 rows][32 lanes]).
template<int NT>
__device__ __forceinline__ void gemm_phase(
    float* smem, const float* Wbase, const float* act,
    int warp, int lane, int tid)
{
    pfA(smem, 0, act, tid);        cp_commit();
    pfA(smem, 1, act + 8192, tid); cp_commit();
    ull acc[16];
#pragma unroll
    for (int j = 0; j < 16; j++) acc[j] = 0ull;
#pragma unroll 1
    for (int kt = 0; kt < NT; kt++) {
        if (kt < NT - 1) asm volatile("cp.async.wait_group 1;");
        else             asm volatile("cp.async.wait_group 0;");
        __syncthreads();
        if (kt < NT - 2) {
            int n = kt + 2;
            pfW(smem, n % 3, Wbase + n * 256, tid);
            pfA(smem, n % 3, act + n * 8192, tid);
            cp_commit();
        }
        const float* w = smem + SM_WB + (kt % 3) * 4096;
        const ull* au = (const ull*)(smem + SM_AB + (kt % 3) * 8192);
        const int k2lo = warp * 8;
#pragma unroll
        for (int k2 = 0; k2 < 8; k2 += 2) {
            ull a0 = au[(k2lo + k2) * 32 + lane];
            ull a1 = au[(k2lo + k2 + 1) * 32 + lane];
#pragma unroll
            for (int j = 0; j < 16; j++) {
                ulonglong2 wv = *(const ulonglong2*)(w + j * 256 + (k2lo + k2) * 2);
                acc[j] = f2fma(a0, wv.x, acc[j]);
                acc[j] = f2fma(a1, wv.y, acc[j]);
            }
        }
    }
    float v[16];
#pragma unroll
    for (int j = 0; j < 16; j++) {
        float2 p = u2f(acc[j]);
        v[j] = p.x + p.y;
    }
    float* sred = smem + SM_SR;
    __syncthreads();
    if (warp >= 8) {
#pragma unroll
        for (int j = 0; j < 16; j++)
            sred[((warp - 8) * 16 + j) * 32 + lane] = v[j];
    }
    __syncthreads();
    if (warp < 8) {
#pragma unroll
        for (int j = 0; j < 16; j++)
            sred[(warp * 16 + j) * 32 + lane] += v[j];
    }
    __syncthreads();
}

// ---------------- persistent CfC scan (512 threads) ----------------
extern __shared__ float s_dyn[];

__global__ __launch_bounds__(512, 1) void k_scan(const float* __restrict__ tsp,
                                                 const float* __restrict__ hid,
                                                 const float* __restrict__ bbb,
                                                 const float* __restrict__ bf1,
                                                 const float* __restrict__ bf2,
                                                 const float* __restrict__ bta,
                                                 const float* __restrict__ btb) {
    float* smem = s_dyn;
    float* sred = smem + SM_SR;
    float* sHa  = sred + 4096;
    float* sHb  = sred + 4608;
    const int tid = threadIdx.x, warp = tid >> 5, lane = tid & 31, bid = blockIdx.x;
    unsigned gen = 0;
    const int j0 = bid * 16;
    const int u0 = bid * 8;
    const float* W0h = g_w0T + (size_t)j0 * 2048 + 1024;    // h-part rows, stride 2048
    const float* W1  = g_w1T + (size_t)j0 * 2048;
    const float* WhA = g_whT + (size_t)bid * 32 * 2048;
    const float* WhB = WhA + 16 * 2048;
    {   // init hidden
        int i = bid * 512 + tid;
        if (i < 32768) {
            int u = i >> 5, b = i & 31;
            g_h[PIDX(u, b)] = hid[b * 1024 + u];
        }
    }
    bar_arrive(gen);
    pfW(smem, 0, W0h, tid);       cp_commit();
    pfW(smem, 1, W0h + 256, tid); cp_commit();
    bar_wait(gen);

    for (int t = 0; t < 512; t++) {
        // ---- backbone layer 0, h-part only (K=1024) ----
        gemm_phase<4>(smem, W0h, g_h, warp, lane, tid);
        {
            int jj = warp;
            float s = g_pre[(size_t)t * 65536 + (size_t)(j0 + jj) * 32 + lane];
#pragma unroll
            for (int w8 = 0; w8 < 8; w8++) s += sred[(w8 * 16 + jj) * 32 + lane];
            g_b1[PIDX(j0 + jj, lane)] = 1.7159f * tanhf(0.666f * s);
        }
        bar_arrive(gen);
        pfW(smem, 0, W1, tid);       cp_commit();
        pfW(smem, 1, W1 + 256, tid); cp_commit();
        bar_wait(gen);
        // ---- backbone layer 1 (K=2048) ----
        gemm_phase<8>(smem, W1, g_b1, warp, lane, tid);
        {
            int jj = warp;
            float s = bbb[2048 + j0 + jj];
#pragma unroll
            for (int w8 = 0; w8 < 8; w8++) s += sred[(w8 * 16 + jj) * 32 + lane];
            g_b2[PIDX(j0 + jj, lane)] = 1.7159f * tanhf(0.666f * s);
        }
        bar_arrive(gen);
        pfW(smem, 0, WhA, tid);       cp_commit();
        pfW(smem, 1, WhA + 256, tid); cp_commit();
        bar_wait(gen);
        // ---- heads pass A: ff1|ff2 rows (block-local) ----
        gemm_phase<8>(smem, WhA, g_b2, warp, lane, tid);
        pfW(smem, 0, WhB, tid);       cp_commit();
        pfW(smem, 1, WhB + 256, tid); cp_commit();
        {
            int jj = warp;
            int u = u0 + (jj & 7);
            float s = (jj < 8) ? bf1[u] : bf2[u];
#pragma unroll
            for (int w8 = 0; w8 < 8; w8++) s += sred[(w8 * 16 + jj) * 32 + lane];
            sHa[jj * 32 + lane] = s;
        }
        // ---- heads pass B: ta|tb rows (block-local) ----
        gemm_phase<8>(smem, WhB, g_b2, warp, lane, tid);
        {
            int jj = warp;
            int u = u0 + (jj & 7);
            float s = (jj < 8) ? bta[u] : btb[u];
#pragma unroll
            for (int w8 = 0; w8 < 8; w8++) s += sred[(w8 * 16 + jj) * 32 + lane];
            sHb[jj * 32 + lane] = s;
        }
        __syncthreads();
        if (warp < 8) {   // fused CfC gate: this block's 8 u-units x 32 batches
            float v1 = tanhf(sHa[warp * 32 + lane]);
            float v2 = tanhf(sHa[(8 + warp) * 32 + lane]);
            float ta = sHb[warp * 32 + lane];
            float tb = sHb[(8 + warp) * 32 + lane];
            float ts = tsp[lane * 512 + t];
            float ti = 1.f / (1.f + expf(-(ta * ts + tb)));
            float hn = v1 + ti * (v2 - v1);
            int p = PIDX(u0 + warp, lane);
            g_h[p] = hn;
            g_co[(size_t)t * 32768 + p] = hn;
        }
        bar_arrive(gen);
        if (t != 511) {
            pfW(smem, 0, W0h, tid);       cp_commit();
            pfW(smem, 1, W0h + 256, tid); cp_commit();
        }
        bar_wait(gen);
    }
}

// ---------------- h_final writeback ----------------
__global__ void k_hf(float* __restrict__ out) {
    int i = blockIdx.x * 256 + threadIdx.x;
    int u = i & 1023, b = i >> 10;
    out[i] = g_h[PIDX(u, b)];
}

// ---------------- host ----------------
extern "C" void kernel_launch(void* const* d_in, const int* in_sizes, int n_in,
                              void* d_out, int out_size) {
    const float* x    = (const float*)d_in[0];
    const float* tsp  = (const float*)d_in[1];
    const float* hid  = (const float*)d_in[2];
    const float* nw   = (const float*)d_in[3];
    const float* nb   = (const float*)d_in[4];
    const float* w_in = (const float*)d_in[5];
    const float* b_in = (const float*)d_in[6];
    const float* bbw  = (const float*)d_in[7];
    const float* bbb  = (const float*)d_in[8];
    const float* wf1  = (const float*)d_in[9];
    const float* bf1  = (const float*)d_in[10];
    const float* wf2  = (const float*)d_in[11];
    const float* bf2  = (const float*)d_in[12];
    const float* wta  = (const float*)d_in[13];
    const float* bta  = (const float*)d_in[14];
    const float* wtb  = (const float*)d_in[15];
    const float* btb  = (const float*)d_in[16];
    const float* w_out= (const float*)d_in[17];
    const float* b_out= (const float*)d_in[18];
    float* y  = (float*)d_out;
    float* hf = y + 16777216;

    static int s_attr_set = 0;
    if (!s_attr_set) {
        cudaFuncSetAttribute(k_scan, cudaFuncAttributeMaxDynamicSharedMemorySize, SCAN_SMEM);
        s_attr_set = 1;
    }

    dim3 tb(32, 8);
    k_tr<<<dim3(64, 64, 8), tb>>>(bbw, w_in, w_out, wf1, wf2, wta, wtb);
    k_ln<<<512, 256>>>(x, nw, nb);
    k_gin<<<dim3(16, 128), 256>>>(b_in);
    k_pre<<<dim3(32, 128), 256>>>(bbb);
    k_scan<<<128, 512, SCAN_SMEM>>>(tsp, hid, bbb, bf1, bf2, bta, btb);
    k_gout<<<dim3(16, 128), 256>>>(b_out, x, y);
    k_hf<<<128, 256>>>(hf);
}

// round 11
// speedup vs baseline: 1.1436x; 1.0945x over previous
#include <cuda_runtime.h>
#include <cuda_bf16.h>
#include <cstdint>

typedef unsigned long long ull;
typedef __nv_bfloat16 bf16;

#define PIDX(k,b) (((((k)>>1))<<6) + (((b))<<1) + ((k)&1))

// ---------------- device scratch ----------------
__device__ __align__(16) float g_xn [512*1024*32];
__device__ __align__(16) float g_cx [512*1024*32];
__device__ __align__(16) float g_co [512*1024*32];
__device__ __align__(16) float g_pre[512*2048*32];   // [t][j][b]
__device__ __align__(16) float g_h  [1024*32];
__device__ __align__(16) float g_winT [1024*1024];
__device__ __align__(16) float g_w0T  [2048*2048];   // for k_pre (x-part)
__device__ __align__(16) float g_woutT[1024*1024];
// MMA fragment-ordered bf16 hi/lo weight planes
__device__ __align__(16) bf16 g_w0F[256*64*256];     // L0 h-part [n8][k16][lane*8]
__device__ __align__(16) bf16 g_w1F[256*128*256];
__device__ __align__(16) bf16 g_whF[512*128*256];    // heads interleaved n8 = u8*4+h
// fragment-ordered activations [k16][mt][pl][lane*8]
__device__ __align__(16) bf16 g_hF [65536];
__device__ __align__(16) bf16 g_b1F[131072];
__device__ __align__(16) bf16 g_b2F[131072];
__device__ unsigned g_bar;

// ---------------- helpers ----------------
__device__ __forceinline__ ull f2fma(ull a, ull b, ull c) {
    ull d; asm("fma.rn.f32x2 %0,%1,%2,%3;" : "=l"(d) : "l"(a), "l"(b), "l"(c));
    return d;
}
__device__ __forceinline__ float2 u2f(ull v) {
    float2 f; asm("mov.b64 {%0,%1},%2;" : "=f"(f.x), "=f"(f.y) : "l"(v));
    return f;
}
__device__ __forceinline__ void cpa16(uint32_t s, const void* g) {
    asm volatile("cp.async.cg.shared.global [%0],[%1],16;" :: "r"(s), "l"(g));
}
__device__ __forceinline__ void cp_commit() { asm volatile("cp.async.commit_group;"); }

#define MMA(C,a0,a1,a2,a3,b0,b1) asm volatile( \
 "mma.sync.aligned.m16n8k16.row.col.f32.bf16.bf16.f32 {%0,%1,%2,%3},{%4,%5,%6,%7},{%8,%9},{%0,%1,%2,%3};" \
 : "+f"(C[0]),"+f"(C[1]),"+f"(C[2]),"+f"(C[3]) \
 : "r"(a0),"r"(a1),"r"(a2),"r"(a3),"r"(b0),"r"(b1))

__device__ __forceinline__ uint32_t pk2bf(float a, float b) {
    __nv_bfloat162 t; t.x = __float2bfloat16(a); t.y = __float2bfloat16(b);
    return *reinterpret_cast<uint32_t*>(&t);
}
// write one fp32 value as hi/lo bf16 into fragment-ordered act buffer
__device__ __forceinline__ void fwr(bf16* base, int k, int m, float v) {
    int k16 = k >> 4, kk = k & 15, mt = m >> 4, r = m & 15;
    int lane = (r & 7) * 4 + ((kk & 7) >> 1);
    int reg  = (r >> 3) + 2 * (kk >> 3), half = kk & 1;
    int o = ((k16 * 2 + mt) * 2) * 256 + lane * 8 + reg * 2 + half;
    bf16 h = __float2bfloat16(v);
    base[o] = h;
    base[o + 256] = __float2bfloat16(v - __bfloat162float(h));
}

__device__ __forceinline__ void bar_arrive(unsigned& gen) {
    __syncthreads();
    gen++;
    if (threadIdx.x == 0) { __threadfence(); atomicAdd(&g_bar, 1u); }
}
__device__ __forceinline__ void bar_wait(unsigned gen) {
    if (threadIdx.x == 0) {
        unsigned tgt = gen * gridDim.x, v;
        do {
            asm volatile("ld.acquire.gpu.u32 %0,[%1];" : "=r"(v) : "l"(&g_bar) : "memory");
        } while (v < tgt);
    }
    __syncthreads();
}

// ---------------- fp32 transposes for pre/post GEMMs (+ bar reset) ----------
__global__ __launch_bounds__(256) void k_tr(const float* __restrict__ bbw,
                                            const float* __restrict__ win,
                                            const float* __restrict__ wout) {
    __shared__ float tile[32][33];
    int z = blockIdx.z, c0 = blockIdx.x * 32, r0 = blockIdx.y * 32;
    int x = threadIdx.x, y = threadIdx.y;
    if (z == 0 && blockIdx.x == 0 && blockIdx.y == 0 && x == 0 && y == 0) g_bar = 0u;
    const float* src; float* dst; int C;
    if (z == 0) { src = bbw; dst = g_w0T; C = 2048; }
    else {
        if (blockIdx.x >= 32 || blockIdx.y >= 32) return;
        src = (z == 1) ? win : wout;
        dst = (z == 1) ? g_winT : g_woutT;
        C = 1024;
    }
#pragma unroll
    for (int i = 0; i < 32; i += 8)
        tile[y + i][x] = src[(size_t)(r0 + y + i) * C + c0 + x];
    __syncthreads();
#pragma unroll
    for (int i = 0; i < 32; i += 8)
        dst[(size_t)(c0 + y + i) * C + r0 + x] = tile[x][y + i];
}

// ---------------- weight -> fragment-ordered bf16 hi/lo ---------------------
__global__ __launch_bounds__(256) void k_wc(const float* __restrict__ bbw,
                                            const float* __restrict__ wf1,
                                            const float* __restrict__ wf2,
                                            const float* __restrict__ wta,
                                            const float* __restrict__ wtb) {
    int lane = threadIdx.x;
    int k16 = blockIdx.x * 8 + threadIdx.y;
    int z = blockIdx.z;
    const float* src; bf16* dst; int ld, nrow; size_t tile;
    if (z == 0) {
        if (k16 >= 64) return;
        src = bbw + (size_t)1024 * 2048; ld = 2048;
        nrow = blockIdx.y * 8 + (lane >> 2);
        dst = g_w0F; tile = (size_t)blockIdx.y * 64 + k16;
    } else if (z == 1) {
        src = bbw + 4194304; ld = 2048;
        nrow = blockIdx.y * 8 + (lane >> 2);
        dst = g_w1F; tile = (size_t)blockIdx.y * 128 + k16;
    } else {
        if (blockIdx.y >= 128) return;
        int h = z - 2;
        src = h == 0 ? wf1 : h == 1 ? wf2 : h == 2 ? wta : wtb;
        ld = 1024;
        nrow = blockIdx.y * 8 + (lane >> 2);   // u
        dst = g_whF; tile = (size_t)(blockIdx.y * 4 + h) * 128 + k16;
    }
    int c = lane & 3, k0 = k16 * 16;
    float v0 = src[(size_t)(k0 + 2 * c)     * ld + nrow];
    float v1 = src[(size_t)(k0 + 2 * c + 1) * ld + nrow];
    float v2 = src[(size_t)(k0 + 8 + 2 * c)     * ld + nrow];
    float v3 = src[(size_t)(k0 + 8 + 2 * c + 1) * ld + nrow];
    float r0 = v0 - __bfloat162float(__float2bfloat16(v0));
    float r1 = v1 - __bfloat162float(__float2bfloat16(v1));
    float r2 = v2 - __bfloat162float(__float2bfloat16(v2));
    float r3 = v3 - __bfloat162float(__float2bfloat16(v3));
    uint4 out;
    out.x = pk2bf(v0, v1); out.y = pk2bf(v2, v3);
    out.z = pk2bf(r0, r1); out.w = pk2bf(r2, r3);
    *reinterpret_cast<uint4*>(dst + tile * 256 + lane * 8) = out;
}

// ---------------- layernorm -> packed xn ----------------
__global__ __launch_bounds__(256) void k_ln(const float* __restrict__ x,
                                            const float* __restrict__ nw,
                                            const float* __restrict__ nb) {
    const int t = blockIdx.x;
    __shared__ float smu[32], srs[32];
    int warp = threadIdx.x >> 5, lane = threadIdx.x & 31;
    for (int b = warp; b < 32; b += 8) {
        const float* row = x + (size_t)b * 524288 + (size_t)t * 1024;
        float s = 0.f, s2 = 0.f;
        for (int d = lane; d < 1024; d += 32) { float v = row[d]; s += v; s2 += v * v; }
#pragma unroll
        for (int o = 16; o; o >>= 1) {
            s  += __shfl_xor_sync(0xffffffffu, s, o);
            s2 += __shfl_xor_sync(0xffffffffu, s2, o);
        }
        if (lane == 0) {
            float mu = s * (1.f / 1024.f);
            float var = s2 * (1.f / 1024.f) - mu * mu;
            smu[b] = mu; srs[b] = rsqrtf(var + 1e-5f);
        }
    }
    __syncthreads();
    float* dst = g_xn + (size_t)t * 32768;
    for (int b = warp; b < 32; b += 8) {
        const float* row = x + (size_t)b * 524288 + (size_t)t * 1024;
        float mu = smu[b], rs = srs[b];
        for (int d = lane; d < 1024; d += 32)
            dst[PIDX(d, b)] = (row[d] - mu) * rs * nw[d] + nb[d];
    }
}

// ---------------- input projection ----------------
__global__ __launch_bounds__(256) void k_gin(const float* __restrict__ bias) {
    const int tid = threadIdx.x, warp = tid >> 5, lane = tid & 31;
    const int j0 = blockIdx.x * 64 + warp * 8;
    const int t0 = blockIdx.y * 4;
    ull acc[4][8];
#pragma unroll
    for (int tt = 0; tt < 4; tt++)
#pragma unroll
        for (int j = 0; j < 8; j++) acc[tt][j] = 0ull;
    const ull* xp = (const ull*)g_xn;
#pragma unroll 1
    for (int k4 = 0; k4 < 256; k4++) {
        ull a0[4], a1[4];
#pragma unroll
        for (int tt = 0; tt < 4; tt++) {
            const ull* ap = xp + (size_t)(t0 + tt) * 16384 + (size_t)(2 * k4) * 32;
            a0[tt] = ap[lane]; a1[tt] = ap[lane + 32];
        }
#pragma unroll
        for (int j = 0; j < 8; j++) {
            ulonglong2 wv = *(const ulonglong2*)(g_winT + (size_t)(j0 + j) * 1024 + 4 * k4);
#pragma unroll
            for (int tt = 0; tt < 4; tt++) {
                acc[tt][j] = f2fma(a0[tt], wv.x, acc[tt][j]);
                acc[tt][j] = f2fma(a1[tt], wv.y, acc[tt][j]);
            }
        }
    }
#pragma unroll
    for (int tt = 0; tt < 4; tt++)
#pragma unroll
        for (int j = 0; j < 8; j++) {
            float2 s = u2f(acc[tt][j]);
            g_cx[(size_t)(t0 + tt) * 32768 + PIDX(j0 + j, lane)] = s.x + s.y + bias[j0 + j];
        }
}

// ---------------- L0 x-part pre-activation ----------------
__global__ __launch_bounds__(256) void k_pre(const float* __restrict__ bbb) {
    const int tid = threadIdx.x, warp = tid >> 5, lane = tid & 31;
    const int j0 = blockIdx.x * 64 + warp * 8;
    const int t0 = blockIdx.y * 4;
    ull acc[4][8];
#pragma unroll
    for (int tt = 0; tt < 4; tt++)
#pragma unroll
        for (int j = 0; j < 8; j++) acc[tt][j] = 0ull;
    const ull* cxp = (const ull*)g_cx;
#pragma unroll 1
    for (int k4 = 0; k4 < 256; k4++) {
        ull a0[4], a1[4];
#pragma unroll
        for (int tt = 0; tt < 4; tt++) {
            const ull* ap = cxp + (size_t)(t0 + tt) * 16384 + (size_t)(2 * k4) * 32;
            a0[tt] = ap[lane]; a1[tt] = ap[lane + 32];
        }
#pragma unroll
        for (int j = 0; j < 8; j++) {
            ulonglong2 wv = *(const ulonglong2*)(g_w0T + (size_t)(j0 + j) * 2048 + 4 * k4);
#pragma unroll
            for (int tt = 0; tt < 4; tt++) {
                acc[tt][j] = f2fma(a0[tt], wv.x, acc[tt][j]);
                acc[tt][j] = f2fma(a1[tt], wv.y, acc[tt][j]);
            }
        }
    }
#pragma unroll
    for (int tt = 0; tt < 4; tt++)
#pragma unroll
        for (int j = 0; j < 8; j++) {
            float2 s = u2f(acc[tt][j]);
            g_pre[(size_t)(t0 + tt) * 65536 + (size_t)(j0 + j) * 32 + lane] =
                s.x + s.y + bbb[j0 + j];
        }
}

// ---------------- output projection + residual ----------------
__global__ __launch_bounds__(256) void k_gout(const float* __restrict__ bias,
                                              const float* __restrict__ x,
                                              float* __restrict__ y) {
    const int tid = threadIdx.x, warp = tid >> 5, lane = tid & 31;
    const int j0 = blockIdx.x * 64 + warp * 8;
    const int t0 = blockIdx.y * 4;
    ull acc[4][8];
#pragma unroll
    for (int tt = 0; tt < 4; tt++)
#pragma unroll
        for (int j = 0; j < 8; j++) acc[tt][j] = 0ull;
    const ull* cp = (const ull*)g_co;
#pragma unroll 1
    for (int k4 = 0; k4 < 256; k4++) {
        ull a0[4], a1[4];
#pragma unroll
        for (int tt = 0; tt < 4; tt++) {
            const ull* ap = cp + (size_t)(t0 + tt) * 16384 + (size_t)(2 * k4) * 32;
            a0[tt] = ap[lane]; a1[tt] = ap[lane + 32];
        }
#pragma unroll
        for (int j = 0; j < 8; j++) {
            ulonglong2 wv = *(const ulonglong2*)(g_woutT + (size_t)(j0 + j) * 1024 + 4 * k4);
#pragma unroll
            for (int tt = 0; tt < 4; tt++) {
                acc[tt][j] = f2fma(a0[tt], wv.x, acc[tt][j]);
                acc[tt][j] = f2fma(a1[tt], wv.y, acc[tt][j]);
            }
        }
    }
#pragma unroll
    for (int tt = 0; tt < 4; tt++)
#pragma unroll
        for (int j = 0; j < 8; j++) {
            int d = j0 + j;
            size_t oi = (size_t)lane * 524288 + (size_t)(t0 + tt) * 1024 + d;
            float2 s = u2f(acc[tt][j]);
            y[oi] = s.x + s.y + bias[d] + x[oi];
        }
}

// ---------------- scan smem layout (bytes) ----------------
#define SM_W 0            // 3 x 16KB weight stage bufs
#define SM_A 49152        // 3 x 16KB act stage bufs
#define SM_R 98304        // 2KB reduction
#define SM_H 100352       // 4KB heads exchange
#define SCAN_SMEM 104448

template<int G>
__device__ __forceinline__ void pfW(char* smem, int buf, const char* wsrc,
                                    int wstride, int tid) {
    uint32_t d = (uint32_t)__cvta_generic_to_shared(smem + SM_W + buf * 16384);
#pragma unroll
    for (int g = 0; g < G; g++)
        cpa16(d + g * 4096 + tid * 16, wsrc + (size_t)g * wstride + tid * 16);
}
__device__ __forceinline__ void pfA(char* smem, int buf, const char* asrc, int tid) {
    uint32_t d = (uint32_t)__cvta_generic_to_shared(smem + SM_A + buf * 16384);
#pragma unroll
    for (int r = 0; r < 4; r++)
        cpa16(d + (r * 256 + tid) * 16, asrc + (size_t)(r * 256 + tid) * 16);
}

// stage = 8 k16 (k-extent 128). Caller must have committed W stage0 as one group.
// G=2: warp -> (mt=w&1, g=(w>>1)&1, k-half=w>>2), reduced into warps 0-3.
// G=4: warp -> (mt=w&1, g=w>>1), full K.
template<int G>
__device__ __forceinline__ void mma_phase(char* smem, const char* wsrc, int wstride,
                                          const char* asrc, int S, float* C,
                                          int warp, int lane, int tid) {
    pfA(smem, 0, asrc, tid); cp_commit();
    pfW<G>(smem, 1, wsrc + 4096, wstride, tid);
    pfA(smem, 1, asrc + 16384, tid); cp_commit();
    C[0] = C[1] = C[2] = C[3] = 0.f;
    int mt, g, klo, khi;
    if (G == 2) { mt = warp & 1; g = (warp >> 1) & 1; klo = (warp >> 2) * 4; khi = klo + 4; }
    else        { mt = warp & 1; g = warp >> 1;       klo = 0;              khi = 8; }
#pragma unroll 1
    for (int s = 0; s < S; s++) {
        if (s < S - 1) asm volatile("cp.async.wait_group 1;");
        else           asm volatile("cp.async.wait_group 0;");
        __syncthreads();
        if (s + 2 < S) {
            pfW<G>(smem, (s + 2) % 3, wsrc + (size_t)(s + 2) * 4096, wstride, tid);
            pfA(smem, (s + 2) % 3, asrc + (size_t)(s + 2) * 16384, tid);
            cp_commit();
        }
        const char* sA = smem + SM_A + (s % 3) * 16384 + mt * 1024 + lane * 16;
        const char* sW = smem + SM_W + (s % 3) * 16384 + g * 4096 + lane * 16;
#pragma unroll
        for (int k = klo; k < khi; k++) {
            uint4 ah = *(const uint4*)(sA + k * 2048);
            uint4 al = *(const uint4*)(sA + k * 2048 + 512);
            uint4 wv = *(const uint4*)(sW + k * 512);
            MMA(C, ah.x, ah.y, ah.z, ah.w, wv.x, wv.y);  // hi x hi
            MMA(C, ah.x, ah.y, ah.z, ah.w, wv.z, wv.w);  // hi x lo
            MMA(C, al.x, al.y, al.z, al.w, wv.x, wv.y);  // lo x hi
        }
    }
    __syncthreads();
    if (G == 2) {       // fold the two k-halves
        float4* sr = (float4*)(smem + SM_R);
        if (warp >= 4) { float4 v = {C[0], C[1], C[2], C[3]}; sr[(warp - 4) * 32 + lane] = v; }
        __syncthreads();
        if (warp < 4) {
            float4 v = sr[warp * 32 + lane];
            C[0] += v.x; C[1] += v.y; C[2] += v.z; C[3] += v.w;
        }
    }
}

// ---------------- persistent CfC scan (MMA) ----------------
extern __shared__ char sdyn[];

__global__ __launch_bounds__(256, 1) void k_scan(const float* __restrict__ tsp,
                                                 const float* __restrict__ hid,
                                                 const float* __restrict__ bbb,
                                                 const float* __restrict__ bf1,
                                                 const float* __restrict__ bf2,
                                                 const float* __restrict__ bta,
                                                 const float* __restrict__ btb) {
    char* smem = sdyn;
    float* sH = (float*)(smem + SM_H);
    const int tid = threadIdx.x, warp = tid >> 5, lane = tid & 31, bid = blockIdx.x;
    unsigned gen = 0;
    float C[4];
    const char* W0 = (const char*)g_w0F + (size_t)bid * 65536;
    const char* W1 = (const char*)g_w1F + (size_t)bid * 131072;
    const char* Wh = (const char*)g_whF + (size_t)bid * 262144;
    {   // init hidden: this CTA's 8 u x 32 b
        int u = bid * 8 + warp;
        float v = hid[(size_t)lane * 1024 + u];
        fwr(g_hF, u, lane, v);
        g_h[PIDX(u, lane)] = v;
    }
    bar_arrive(gen);
    pfW<2>(smem, 0, W0, 32768, tid); cp_commit();
    bar_wait(gen);

    for (int t = 0; t < 512; t++) {
        // ---- L0 h-part (K=1024, 16 out rows) ----
        mma_phase<2>(smem, W0, 32768, (const char*)g_hF, 8, C, warp, lane, tid);
        if (warp < 4) {
            int mt = warp & 1, g = (warp >> 1) & 1;
#pragma unroll
            for (int i = 0; i < 4; i++) {
                int r = (lane >> 2) + (i >> 1) * 8, n = 2 * (lane & 3) + (i & 1);
                int j = bid * 16 + g * 8 + n, b = mt * 16 + r;
                float s = C[i] + g_pre[(size_t)t * 65536 + (size_t)j * 32 + b];
                fwr(g_b1F, j, b, 1.7159f * tanhf(0.666f * s));
            }
        }
        bar_arrive(gen);
        pfW<2>(smem, 0, W1, 65536, tid); cp_commit();
        bar_wait(gen);
        // ---- L1 (K=2048, 16 out rows) ----
        mma_phase<2>(smem, W1, 65536, (const char*)g_b1F, 16, C, warp, lane, tid);
        if (warp < 4) {
            int mt = warp & 1, g = (warp >> 1) & 1;
#pragma unroll
            for (int i = 0; i < 4; i++) {
                int r = (lane >> 2) + (i >> 1) * 8, n = 2 * (lane & 3) + (i & 1);
                int j = bid * 16 + g * 8 + n, b = mt * 16 + r;
                float s = C[i] + bbb[2048 + j];
                fwr(g_b2F, j, b, 1.7159f * tanhf(0.666f * s));
            }
        }
        bar_arrive(gen);
        pfW<4>(smem, 0, Wh, 65536, tid); cp_commit();
        bar_wait(gen);
        // ---- heads (K=2048, 32 out rows = 4 heads x 8 u), block-local ----
        mma_phase<4>(smem, Wh, 65536, (const char*)g_b2F, 16, C, warp, lane, tid);
        {
            int mt = warp & 1, g = warp >> 1;
            const float* bp = g == 0 ? bf1 : g == 1 ? bf2 : g == 2 ? bta : btb;
#pragma unroll
            for (int i = 0; i < 4; i++) {
                int r = (lane >> 2) + (i >> 1) * 8, n = 2 * (lane & 3) + (i & 1);
                int b = mt * 16 + r;
                sH[(g * 8 + n) * 32 + b] = C[i] + bp[bid * 8 + n];
            }
        }
        __syncthreads();
        {   // fused CfC gate
            float v1 = tanhf(sH[warp * 32 + lane]);
            float v2 = tanhf(sH[(8 + warp) * 32 + lane]);
            float ta = sH[(16 + warp) * 32 + lane];
            float tb = sH[(24 + warp) * 32 + lane];
            float ts = tsp[lane * 512 + t];
            float ti = 1.f / (1.f + expf(-(ta * ts + tb)));
            float hn = v1 + ti * (v2 - v1);
            int u = bid * 8 + warp;
            fwr(g_hF, u, lane, hn);
            int p = PIDX(u, lane);
            g_h[p] = hn;
            g_co[(size_t)t * 32768 + p] = hn;
        }
        bar_arrive(gen);
        if (t < 511) { pfW<2>(smem, 0, W0, 32768, tid); cp_commit(); }
        bar_wait(gen);
    }
}

// ---------------- h_final writeback ----------------
__global__ void k_hf(float* __restrict__ out) {
    int i = blockIdx.x * 256 + threadIdx.x;
    int u = i & 1023, b = i >> 10;
    out[i] = g_h[PIDX(u, b)];
}

// ---------------- host ----------------
extern "C" void kernel_launch(void* const* d_in, const int* in_sizes, int n_in,
                              void* d_out, int out_size) {
    const float* x    = (const float*)d_in[0];
    const float* tsp  = (const float*)d_in[1];
    const float* hid  = (const float*)d_in[2];
    const float* nw   = (const float*)d_in[3];
    const float* nb   = (const float*)d_in[4];
    const float* w_in = (const float*)d_in[5];
    const float* b_in = (const float*)d_in[6];
    const float* bbw  = (const float*)d_in[7];
    const float* bbb  = (const float*)d_in[8];
    const float* wf1  = (const float*)d_in[9];
    const float* bf1  = (const float*)d_in[10];
    const float* wf2  = (const float*)d_in[11];
    const float* bf2  = (const float*)d_in[12];
    const float* wta  = (const float*)d_in[13];
    const float* bta  = (const float*)d_in[14];
    const float* wtb  = (const float*)d_in[15];
    const float* btb  = (const float*)d_in[16];
    const float* w_out= (const float*)d_in[17];
    const float* b_out= (const float*)d_in[18];
    float* y  = (float*)d_out;
    float* hf = y + 16777216;

    static int s_attr_set = 0;
    if (!s_attr_set) {
        cudaFuncSetAttribute(k_scan, cudaFuncAttributeMaxDynamicSharedMemorySize, SCAN_SMEM);
        s_attr_set = 1;
    }

    dim3 tb(32, 8);
    k_tr<<<dim3(64, 64, 3), tb>>>(bbw, w_in, w_out);
    k_wc<<<dim3(16, 256, 6), tb>>>(bbw, wf1, wf2, wta, wtb);
    k_ln<<<512, 256>>>(x, nw, nb);
    k_gin<<<dim3(16, 128), 256>>>(b_in);
    k_pre<<<dim3(32, 128), 256>>>(bbb);
    k_scan<<<128, 256, SCAN_SMEM>>>(tsp, hid, bbb, bf1, bf2, bta, btb);
    k_gout<<<dim3(16, 128), 256>>>(b_out, x, y);
    k_hf<<<128, 256>>>(hf);
}

// round 13
// speedup vs baseline: 1.1876x; 1.0385x over previous
#include <cuda_runtime.h>
#include <cuda_bf16.h>
#include <cstdint>

typedef unsigned long long ull;
typedef __nv_bfloat16 bf16;

#define PIDX(k,b) (((((k)>>1))<<6) + (((b))<<1) + ((k)&1))

// ---------------- device scratch ----------------
__device__ __align__(16) float g_xn [512*1024*32];
__device__ __align__(16) float g_cx [512*1024*32];
__device__ __align__(16) float g_co [512*1024*32];
__device__ __align__(16) float g_pre[512*2048*32];   // [t][j][b]
__device__ __align__(16) float g_h  [1024*32];
__device__ __align__(16) float g_winT [1024*1024];
__device__ __align__(16) float g_w0T  [2048*2048];   // for k_pre (x-part)
__device__ __align__(16) float g_woutT[1024*1024];
// MMA fragment-ordered bf16 hi/lo weight planes
__device__ __align__(16) bf16 g_w0F[256*64*256];     // L0 h-part
__device__ __align__(16) bf16 g_w1F[256*128*256];
__device__ __align__(16) bf16 g_whF[512*128*256];    // heads interleaved
// fragment-ordered activations; hF is parity double-buffered
__device__ __align__(16) bf16 g_hF [2*65536];
__device__ __align__(16) bf16 g_b1F[131072];
__device__ __align__(16) bf16 g_b2F[131072];
// dataflow counters (128B padded: index*32)
__device__ unsigned g_chs[8*32];
__device__ unsigned g_cb1[16*32];
__device__ unsigned g_cb2[16*32];

// ---------------- helpers ----------------
__device__ __forceinline__ ull f2fma(ull a, ull b, ull c) {
    ull d; asm("fma.rn.f32x2 %0,%1,%2,%3;" : "=l"(d) : "l"(a), "l"(b), "l"(c));
    return d;
}
__device__ __forceinline__ float2 u2f(ull v) {
    float2 f; asm("mov.b64 {%0,%1},%2;" : "=f"(f.x), "=f"(f.y) : "l"(v));
    return f;
}
__device__ __forceinline__ void cpa16(uint32_t s, const void* g) {
    asm volatile("cp.async.cg.shared.global [%0],[%1],16;" :: "r"(s), "l"(g));
}
__device__ __forceinline__ void cp_commit() { asm volatile("cp.async.commit_group;"); }
__device__ __forceinline__ void poll(const unsigned* c, unsigned tgt) {
    unsigned v;
    do { asm volatile("ld.acquire.gpu.u32 %0,[%1];" : "=r"(v) : "l"(c) : "memory"); }
    while (v < tgt);
}

#define MMA(C,a0,a1,a2,a3,b0,b1) asm volatile( \
 "mma.sync.aligned.m16n8k16.row.col.f32.bf16.bf16.f32 {%0,%1,%2,%3},{%4,%5,%6,%7},{%8,%9},{%0,%1,%2,%3};" \
 : "+f"(C[0]),"+f"(C[1]),"+f"(C[2]),"+f"(C[3]) \
 : "r"(a0),"r"(a1),"r"(a2),"r"(a3),"r"(b0),"r"(b1))

__device__ __forceinline__ uint32_t pk2bf(float a, float b) {
    __nv_bfloat162 t; t.x = __float2bfloat16(a); t.y = __float2bfloat16(b);
    return *reinterpret_cast<uint32_t*>(&t);
}
// write one fp32 value as hi/lo bf16 into fragment-ordered act buffer
__device__ __forceinline__ void fwr(bf16* base, int k, int m, float v) {
    int k16 = k >> 4, kk = k & 15, mt = m >> 4, r = m & 15;
    int lane = (r & 7) * 4 + ((kk & 7) >> 1);
    int reg  = (r >> 3) + 2 * (kk >> 3), half = kk & 1;
    int o = ((k16 * 2 + mt) * 2) * 256 + lane * 8 + reg * 2 + half;
    bf16 h = __float2bfloat16(v);
    base[o] = h;
    base[o + 256] = __float2bfloat16(v - __bfloat162float(h));
}

// ---------------- counter reset (every launch; graph-replay safe) ----------
__global__ void k_cinit() {
    int i = threadIdx.x;
    if (i < 256) g_chs[i] = 0u;
    g_cb1[i] = 0u;
    g_cb2[i] = 0u;
}

// ---------------- fp32 transposes for pre/post GEMMs ----------
__global__ __launch_bounds__(256) void k_tr(const float* __restrict__ bbw,
                                            const float* __restrict__ win,
                                            const float* __restrict__ wout) {
    __shared__ float tile[32][33];
    int z = blockIdx.z, c0 = blockIdx.x * 32, r0 = blockIdx.y * 32;
    int x = threadIdx.x, y = threadIdx.y;
    const float* src; float* dst; int C;
    if (z == 0) { src = bbw; dst = g_w0T; C = 2048; }
    else {
        if (blockIdx.x >= 32 || blockIdx.y >= 32) return;
        src = (z == 1) ? win : wout;
        dst = (z == 1) ? g_winT : g_woutT;
        C = 1024;
    }
#pragma unroll
    for (int i = 0; i < 32; i += 8)
        tile[y + i][x] = src[(size_t)(r0 + y + i) * C + c0 + x];
    __syncthreads();
#pragma unroll
    for (int i = 0; i < 32; i += 8)
        dst[(size_t)(c0 + y + i) * C + r0 + x] = tile[x][y + i];
}

// ---------------- weight -> fragment-ordered bf16 hi/lo ---------------------
__global__ __launch_bounds__(256) void k_wc(const float* __restrict__ bbw,
                                            const float* __restrict__ wf1,
                                            const float* __restrict__ wf2,
                                            const float* __restrict__ wta,
                                            const float* __restrict__ wtb) {
    int lane = threadIdx.x;
    int k16 = blockIdx.x * 8 + threadIdx.y;
    int z = blockIdx.z;
    const float* src; bf16* dst; int ld, nrow; size_t tile;
    if (z == 0) {
        if (k16 >= 64) return;
        src = bbw + (size_t)1024 * 2048; ld = 2048;
        nrow = blockIdx.y * 8 + (lane >> 2);
        dst = g_w0F; tile = (size_t)blockIdx.y * 64 + k16;
    } else if (z == 1) {
        src = bbw + 4194304; ld = 2048;
        nrow = blockIdx.y * 8 + (lane >> 2);
        dst = g_w1F; tile = (size_t)blockIdx.y * 128 + k16;
    } else {
        if (blockIdx.y >= 128) return;
        int h = z - 2;
        src = h == 0 ? wf1 : h == 1 ? wf2 : h == 2 ? wta : wtb;
        ld = 1024;
        nrow = blockIdx.y * 8 + (lane >> 2);
        dst = g_whF; tile = (size_t)(blockIdx.y * 4 + h) * 128 + k16;
    }
    int c = lane & 3, k0 = k16 * 16;
    float v0 = src[(size_t)(k0 + 2 * c)     * ld + nrow];
    float v1 = src[(size_t)(k0 + 2 * c + 1) * ld + nrow];
    float v2 = src[(size_t)(k0 + 8 + 2 * c)     * ld + nrow];
    float v3 = src[(size_t)(k0 + 8 + 2 * c + 1) * ld + nrow];
    float r0 = v0 - __bfloat162float(__float2bfloat16(v0));
    float r1 = v1 - __bfloat162float(__float2bfloat16(v1));
    float r2 = v2 - __bfloat162float(__float2bfloat16(v2));
    float r3 = v3 - __bfloat162float(__float2bfloat16(v3));
    uint4 out;
    out.x = pk2bf(v0, v1); out.y = pk2bf(v2, v3);
    out.z = pk2bf(r0, r1); out.w = pk2bf(r2, r3);
    *reinterpret_cast<uint4*>(dst + tile * 256 + lane * 8) = out;
}

// ---------------- layernorm -> packed xn ----------------
__global__ __launch_bounds__(256) void k_ln(const float* __restrict__ x,
                                            const float* __restrict__ nw,
                                            const float* __restrict__ nb) {
    const int t = blockIdx.x;
    __shared__ float smu[32], srs[32];
    int warp = threadIdx.x >> 5, lane = threadIdx.x & 31;
    for (int b = warp; b < 32; b += 8) {
        const float* row = x + (size_t)b * 524288 + (size_t)t * 1024;
        float s = 0.f, s2 = 0.f;
        for (int d = lane; d < 1024; d += 32) { float v = row[d]; s += v; s2 += v * v; }
#pragma unroll
        for (int o = 16; o; o >>= 1) {
            s  += __shfl_xor_sync(0xffffffffu, s, o);
            s2 += __shfl_xor_sync(0xffffffffu, s2, o);
        }
        if (lane == 0) {
            float mu = s * (1.f / 1024.f);
            float var = s2 * (1.f / 1024.f) - mu * mu;
            smu[b] = mu; srs[b] = rsqrtf(var + 1e-5f);
        }
    }
    __syncthreads();
    float* dst = g_xn + (size_t)t * 32768;
    for (int b = warp; b < 32; b += 8) {
        const float* row = x + (size_t)b * 524288 + (size_t)t * 1024;
        float mu = smu[b], rs = srs[b];
        for (int d = lane; d < 1024; d += 32)
            dst[PIDX(d, b)] = (row[d] - mu) * rs * nw[d] + nb[d];
    }
}

// ---------------- input projection ----------------
__global__ __launch_bounds__(256) void k_gin(const float* __restrict__ bias) {
    const int tid = threadIdx.x, warp = tid >> 5, lane = tid & 31;
    const int j0 = blockIdx.x * 64 + warp * 8;
    const int t0 = blockIdx.y * 4;
    ull acc[4][8];
#pragma unroll
    for (int tt = 0; tt < 4; tt++)
#pragma unroll
        for (int j = 0; j < 8; j++) acc[tt][j] = 0ull;
    const ull* xp = (const ull*)g_xn;
#pragma unroll 1
    for (int k4 = 0; k4 < 256; k4++) {
        ull a0[4], a1[4];
#pragma unroll
        for (int tt = 0; tt < 4; tt++) {
            const ull* ap = xp + (size_t)(t0 + tt) * 16384 + (size_t)(2 * k4) * 32;
            a0[tt] = ap[lane]; a1[tt] = ap[lane + 32];
        }
#pragma unroll
        for (int j = 0; j < 8; j++) {
            ulonglong2 wv = *(const ulonglong2*)(g_winT + (size_t)(j0 + j) * 1024 + 4 * k4);
#pragma unroll
            for (int tt = 0; tt < 4; tt++) {
                acc[tt][j] = f2fma(a0[tt], wv.x, acc[tt][j]);
                acc[tt][j] = f2fma(a1[tt], wv.y, acc[tt][j]);
            }
        }
    }
#pragma unroll
    for (int tt = 0; tt < 4; tt++)
#pragma unroll
        for (int j = 0; j < 8; j++) {
            float2 s = u2f(acc[tt][j]);
            g_cx[(size_t)(t0 + tt) * 32768 + PIDX(j0 + j, lane)] = s.x + s.y + bias[j0 + j];
        }
}

// ---------------- L0 x-part pre-activation ----------------
__global__ __launch_bounds__(256) void k_pre(const float* __restrict__ bbb) {
    const int tid = threadIdx.x, warp = tid >> 5, lane = tid & 31;
    const int j0 = blockIdx.x * 64 + warp * 8;
    const int t0 = blockIdx.y * 4;
    ull acc[4][8];
#pragma unroll
    for (int tt = 0; tt < 4; tt++)
#pragma unroll
        for (int j = 0; j < 8; j++) acc[tt][j] = 0ull;
    const ull* cxp = (const ull*)g_cx;
#pragma unroll 1
    for (int k4 = 0; k4 < 256; k4++) {
        ull a0[4], a1[4];
#pragma unroll
        for (int tt = 0; tt < 4; tt++) {
            const ull* ap = cxp + (size_t)(t0 + tt) * 16384 + (size_t)(2 * k4) * 32;
            a0[tt] = ap[lane]; a1[tt] = ap[lane + 32];
        }
#pragma unroll
        for (int j = 0; j < 8; j++) {
            ulonglong2 wv = *(const ulonglong2*)(g_w0T + (size_t)(j0 + j) * 2048 + 4 * k4);
#pragma unroll
            for (int tt = 0; tt < 4; tt++) {
                acc[tt][j] = f2fma(a0[tt], wv.x, acc[tt][j]);
                acc[tt][j] = f2fma(a1[tt], wv.y, acc[tt][j]);
            }
        }
    }
#pragma unroll
    for (int tt = 0; tt < 4; tt++)
#pragma unroll
        for (int j = 0; j < 8; j++) {
            float2 s = u2f(acc[tt][j]);
            g_pre[(size_t)(t0 + tt) * 65536 + (size_t)(j0 + j) * 32 + lane] =
                s.x + s.y + bbb[j0 + j];
        }
}

// ---------------- output projection + residual ----------------
__global__ __launch_bounds__(256) void k_gout(const float* __restrict__ bias,
                                              const float* __restrict__ x,
                                              float* __restrict__ y) {
    const int tid = threadIdx.x, warp = tid >> 5, lane = tid & 31;
    const int j0 = blockIdx.x * 64 + warp * 8;
    const int t0 = blockIdx.y * 4;
    ull acc[4][8];
#pragma unroll
    for (int tt = 0; tt < 4; tt++)
#pragma unroll
        for (int j = 0; j < 8; j++) acc[tt][j] = 0ull;
    const ull* cp = (const ull*)g_co;
#pragma unroll 1
    for (int k4 = 0; k4 < 256; k4++) {
        ull a0[4], a1[4];
#pragma unroll
        for (int tt = 0; tt < 4; tt++) {
            const ull* ap = cp + (size_t)(t0 + tt) * 16384 + (size_t)(2 * k4) * 32;
            a0[tt] = ap[lane]; a1[tt] = ap[lane + 32];
        }
#pragma unroll
        for (int j = 0; j < 8; j++) {
            ulonglong2 wv = *(const ulonglong2*)(g_woutT + (size_t)(j0 + j) * 1024 + 4 * k4);
#pragma unroll
            for (int tt = 0; tt < 4; tt++) {
                acc[tt][j] = f2fma(a0[tt], wv.x, acc[tt][j]);
                acc[tt][j] = f2fma(a1[tt], wv.y, acc[tt][j]);
            }
        }
    }
#pragma unroll
    for (int tt = 0; tt < 4; tt++)
#pragma unroll
        for (int j = 0; j < 8; j++) {
            int d = j0 + j;
            size_t oi = (size_t)lane * 524288 + (size_t)(t0 + tt) * 1024 + d;
            float2 s = u2f(acc[tt][j]);
            y[oi] = s.x + s.y + bias[d] + x[oi];
        }
}

// ---------------- scan smem layout (bytes) ----------------
#define SM_W 0            // 3 x 16KB weight stage bufs
#define SM_A 49152        // 3 x 16KB act stage bufs
#define SM_R 98304        // 2KB reduction
#define SM_H 100352       // 4KB heads exchange
#define SCAN_SMEM 104448

template<int G>
__device__ __forceinline__ void pfW(char* smem, int buf, const char* wsrc,
                                    int wstride, int tid) {
    uint32_t d = (uint32_t)__cvta_generic_to_shared(smem + SM_W + buf * 16384);
#pragma unroll
    for (int g = 0; g < G; g++)
        cpa16(d + g * 4096 + tid * 16, wsrc + (size_t)g * wstride + tid * 16);
}
__device__ __forceinline__ void pfA(char* smem, int buf, const char* asrc, int tid) {
    uint32_t d = (uint32_t)__cvta_generic_to_shared(smem + SM_A + buf * 16384);
#pragma unroll
    for (int r = 0; r < 4; r++)
        cpa16(d + (r * 256 + tid) * 16, asrc + (size_t)(r * 256 + tid) * 16);
}

// Self-timed phase: stage s readiness gated by ctr[s*32] >= tgt (acquire poll,
// overlapped with cp.async waits). G=2 splits K across warp pairs (reduced
// into warps 0-3); G=4 full-K per warp.
template<int G>
__device__ __forceinline__ void mma_phase(char* smem, const char* wsrc, int wstride,
                                          const char* asrc, int S, float* C,
                                          const unsigned* ctr, unsigned tgt,
                                          int warp, int lane, int tid) {
    if (tid == 0) poll(ctr, tgt);
    __syncthreads();
    pfW<G>(smem, 0, wsrc, wstride, tid);
    pfA(smem, 0, asrc, tid); cp_commit();
    if (tid == 0) poll(ctr + 32, tgt);
    __syncthreads();
    pfW<G>(smem, 1, wsrc + 4096, wstride, tid);
    pfA(smem, 1, asrc + 16384, tid); cp_commit();
    C[0] = C[1] = C[2] = C[3] = 0.f;
    int mt, g, klo, khi;
    if (G == 2) { mt = warp & 1; g = (warp >> 1) & 1; klo = (warp >> 2) * 4; khi = klo + 4; }
    else        { mt = warp & 1; g = warp >> 1;       klo = 0;              khi = 8; }
#pragma unroll 1
    for (int s = 0; s < S; s++) {
        if (s + 2 < S && tid == 0) poll(ctr + (s + 2) * 32, tgt);
        if (s < S - 1) asm volatile("cp.async.wait_group 1;");
        else           asm volatile("cp.async.wait_group 0;");
        __syncthreads();
        if (s + 2 < S) {
            pfW<G>(smem, (s + 2) % 3, wsrc + (size_t)(s + 2) * 4096, wstride, tid);
            pfA(smem, (s + 2) % 3, asrc + (size_t)(s + 2) * 16384, tid);
            cp_commit();
        }
        const char* sA = smem + SM_A + (s % 3) * 16384 + mt * 1024 + lane * 16;
        const char* sW = smem + SM_W + (s % 3) * 16384 + g * 4096 + lane * 16;
#pragma unroll
        for (int k = klo; k < khi; k++) {
            uint4 ah = *(const uint4*)(sA + k * 2048);
            uint4 al = *(const uint4*)(sA + k * 2048 + 512);
            uint4 wv = *(const uint4*)(sW + k * 512);
            MMA(C, ah.x, ah.y, ah.z, ah.w, wv.x, wv.y);
            MMA(C, ah.x, ah.y, ah.z, ah.w, wv.z, wv.w);
            MMA(C, al.x, al.y, al.z, al.w, wv.x, wv.y);
        }
    }
    __syncthreads();
    if (G == 2) {
        float4* sr = (float4*)(smem + SM_R);
        if (warp >= 4) { float4 v = {C[0], C[1], C[2], C[3]}; sr[(warp - 4) * 32 + lane] = v; }
        __syncthreads();
        if (warp < 4) {
            float4 v = sr[warp * 32 + lane];
            C[0] += v.x; C[1] += v.y; C[2] += v.z; C[3] += v.w;
        }
    }
}

// ---------------- persistent CfC scan (self-timed dataflow) ----------------
extern __shared__ char sdyn[];

__global__ __launch_bounds__(256, 1) void k_scan(const float* __restrict__ tsp,
                                                 const float* __restrict__ hid,
                                                 const float* __restrict__ bbb,
                                                 const float* __restrict__ bf1,
                                                 const float* __restrict__ bf2,
                                                 const float* __restrict__ bta,
                                                 const float* __restrict__ btb) {
    char* smem = sdyn;
    float* sH = (float*)(smem + SM_H);
    const int tid = threadIdx.x, warp = tid >> 5, lane = tid & 31, bid = blockIdx.x;
    float C[4];
    const char* W0 = (const char*)g_w0F + (size_t)bid * 65536;
    const char* W1 = (const char*)g_w1F + (size_t)bid * 131072;
    const char* Wh = (const char*)g_whF + (size_t)bid * 262144;
    {   // init hidden: this CTA's 8 u x 32 b -> hF parity buffer 1
        int u = bid * 8 + warp;
        float v = hid[(size_t)lane * 1024 + u];
        fwr(g_hF + 65536, u, lane, v);
        g_h[PIDX(u, lane)] = v;
    }
    __threadfence();
    __syncthreads();
    if (tid == 0) atomicAdd(&g_chs[(bid >> 4) * 32], 1u);

    for (int t = 0; t < 512; t++) {
        // ---- L0 h-part (K=1024): h written at step t-1 (parity !(t&1)) ----
        mma_phase<2>(smem, W0, 32768,
                     (const char*)(g_hF + ((t & 1) ^ 1) * 65536), 8, C,
                     g_chs, 16u * (unsigned)(t + 1), warp, lane, tid);
        if (warp < 4) {
            int mt = warp & 1, g = (warp >> 1) & 1;
#pragma unroll
            for (int i = 0; i < 4; i++) {
                int r = (lane >> 2) + (i >> 1) * 8, n = 2 * (lane & 3) + (i & 1);
                int j = bid * 16 + g * 8 + n, b = mt * 16 + r;
                float s = C[i] + g_pre[(size_t)t * 65536 + (size_t)j * 32 + b];
                fwr(g_b1F, j, b, 1.7159f * tanhf(0.666f * s));
            }
        }
        __threadfence();
        __syncthreads();
        if (tid == 0) atomicAdd(&g_cb1[(bid >> 3) * 32], 1u);

        // ---- L1 (K=2048) ----
        mma_phase<2>(smem, W1, 65536, (const char*)g_b1F, 16, C,
                     g_cb1, 8u * (unsigned)(t + 1), warp, lane, tid);
        if (warp < 4) {
            int mt = warp & 1, g = (warp >> 1) & 1;
#pragma unroll
            for (int i = 0; i < 4; i++) {
                int r = (lane >> 2) + (i >> 1) * 8, n = 2 * (lane & 3) + (i & 1);
                int j = bid * 16 + g * 8 + n, b = mt * 16 + r;
                float s = C[i] + bbb[2048 + j];
                fwr(g_b2F, j, b, 1.7159f * tanhf(0.666f * s));
            }
        }
        __threadfence();
        __syncthreads();
        if (tid == 0) atomicAdd(&g_cb2[(bid >> 3) * 32], 1u);

        // ---- heads (K=2048, 32 rows = 4 heads x 8 u), block-local ----
        mma_phase<4>(smem, Wh, 65536, (const char*)g_b2F, 16, C,
                     g_cb2, 8u * (unsigned)(t + 1), warp, lane, tid);
        {
            int mt = warp & 1, g = warp >> 1;
            const float* bp = g == 0 ? bf1 : g == 1 ? bf2 : g == 2 ? bta : btb;
#pragma unroll
            for (int i = 0; i < 4; i++) {
                int r = (lane >> 2) + (i >> 1) * 8, n = 2 * (lane & 3) + (i & 1);
                int b = mt * 16 + r;
                sH[(g * 8 + n) * 32 + b] = C[i] + bp[bid * 8 + n];
            }
        }
        __syncthreads();
        {   // fused CfC gate -> hF parity t&1
            float v1 = tanhf(sH[warp * 32 + lane]);
            float v2 = tanhf(sH[(8 + warp) * 32 + lane]);
            float ta = sH[(16 + warp) * 32 + lane];
            float tb = sH[(24 + warp) * 32 + lane];
            float ts = tsp[lane * 512 + t];
            float ti = 1.f / (1.f + expf(-(ta * ts + tb)));
            float hn = v1 + ti * (v2 - v1);
            int u = bid * 8 + warp;
            fwr(g_hF + (t & 1) * 65536, u, lane, hn);
            int p = PIDX(u, lane);
            g_h[p] = hn;
            g_co[(size_t)t * 32768 + p] = hn;
        }
        __threadfence();
        __syncthreads();
        if (tid == 0) atomicAdd(&g_chs[(bid >> 4) * 32], 1u);
    }
}

// ---------------- h_final writeback ----------------
__global__ void k_hf(float* __restrict__ out) {
    int i = blockIdx.x * 256 + threadIdx.x;
    int u = i & 1023, b = i >> 10;
    out[i] = g_h[PIDX(u, b)];
}

// ---------------- host ----------------
extern "C" void kernel_launch(void* const* d_in, const int* in_sizes, int n_in,
                              void* d_out, int out_size) {
    const float* x    = (const float*)d_in[0];
    const float* tsp  = (const float*)d_in[1];
    const float* hid  = (const float*)d_in[2];
    const float* nw   = (const float*)d_in[3];
    const float* nb   = (const float*)d_in[4];
    const float* w_in = (const float*)d_in[5];
    const float* b_in = (const float*)d_in[6];
    const float* bbw  = (const float*)d_in[7];
    const float* bbb  = (const float*)d_in[8];
    const float* wf1  = (const float*)d_in[9];
    const float* bf1  = (const float*)d_in[10];
    const float* wf2  = (const float*)d_in[11];
    const float* bf2  = (const float*)d_in[12];
    const float* wta  = (const float*)d_in[13];
    const float* bta  = (const float*)d_in[14];
    const float* wtb  = (const float*)d_in[15];
    const float* btb  = (const float*)d_in[16];
    const float* w_out= (const float*)d_in[17];
    const float* b_out= (const float*)d_in[18];
    float* y  = (float*)d_out;
    float* hf = y + 16777216;

    static int s_attr_set = 0;
    if (!s_attr_set) {
        cudaFuncSetAttribute(k_scan, cudaFuncAttributeMaxDynamicSharedMemorySize, SCAN_SMEM);
        s_attr_set = 1;
    }

    dim3 tb(32, 8);
    k_cinit<<<1, 512>>>();
    k_tr<<<dim3(64, 64, 3), tb>>>(bbw, w_in, w_out);
    k_wc<<<dim3(16, 256, 6), tb>>>(bbw, wf1, wf2, wta, wtb);
    k_ln<<<512, 256>>>(x, nw, nb);
    k_gin<<<dim3(16, 128), 256>>>(b_in);
    k_pre<<<dim3(32, 128), 256>>>(bbb);
    k_scan<<<128, 256, SCAN_SMEM>>>(tsp, hid, bbb, bf1, bf2, bta, btb);
    k_gout<<<dim3(16, 128), 256>>>(b_out, x, y);
    k_hf<<<128, 256>>>(hf);
}